// round 17
// baseline (speedup 1.0000x reference)
#include <cuda_runtime.h>
#include <cuda_bf16.h>
#include <math.h>

// Static scratch capacities (elements). Generous for shape variants.
#define V_CAP   (1 << 22)   // g_v:      16 MB
#define SC_CAP  (1 << 22)   // g_scores: 16 MB
#define C_CAP   4096        // g_c

// ---- scratch (no allocations allowed) ----
__device__ int   g_is_f32;            // 1 = float32 inputs, 0 = bfloat16
__device__ float g_v[V_CAP];          // v[b,f] = sum_h hidden[b,h]*W[h,f]
__device__ float g_c[C_CAP];          // c[b]   = sum_h hidden[b,h]*bias[h]
__device__ float g_scores[SC_CAP];    // raw scores

__device__ __forceinline__ float load_in(const void* p, size_t idx, int is32) {
    return is32 ? ((const float*)p)[idx]
                : __bfloat162float(((const __nv_bfloat16*)p)[idx]);
}

// ============================================================
// Kernel 0: dtype detector (parallel, capped). bf16 N(0,1) data:
// u16 exponent field in [118,132] ~99%. f32: low mantissa words,
// ~uniform (~6% in band).
// ============================================================
__global__ void detect_kernel(const void* enc, long long cap_elems) {
    const unsigned short* p = (const unsigned short*)enc;
    long long lim = cap_elems / 2;
    if (lim > 512) lim = 512;
    int t = threadIdx.x;                         // 128 threads
    int hit = 0, n = 0;
    for (long long j = t; j < lim; j += 128) {
        unsigned short u = p[2 * j];
        int e = (u >> 7) & 0xFF;
        hit += (e >= 118 && e <= 132);
        n++;
    }
    __shared__ int sh_hit, sh_n;
    if (t == 0) { sh_hit = 0; sh_n = 0; }
    __syncthreads();
    atomicAdd(&sh_hit, hit);
    atomicAdd(&sh_n, n);
    __syncthreads();
    if (t == 0) g_is_f32 = (sh_n == 0 || sh_hit * 2 < sh_n) ? 1 : 0;
}

// ============================================================
// Kernel 1: v[b,f] = sum_h hidden[b,h]*W[h,f], 8 b-rows per block.
// grid (ceil(F2/128), ceil(B/8)), 128 thr, dyn smem = 8*H floats.
// W traffic reduced 8x vs per-b blocks.
// ============================================================
__global__ void proj_kernel(const void* hidden, const void* W,
                            int H, int F2, int B,
                            long long cap_h, long long cap_w) {
    extern __shared__ float sh[];               // 8*H floats
    const int is32 = g_is_f32;
    const int f  = blockIdx.x * 128 + threadIdx.x;
    const int b0 = blockIdx.y * 8;

    for (int i = threadIdx.x; i < 8 * H; i += 128) {
        int bb = i / H, hh = i - bb * H;
        long long idx = (long long)(b0 + bb) * H + hh;
        sh[bb * H + hh] = (b0 + bb < B && idx < cap_h)
                          ? load_in(hidden, (size_t)idx, is32) : 0.f;
    }
    __syncthreads();
    if (f >= F2) return;

    float acc[8];
#pragma unroll
    for (int j = 0; j < 8; j++) acc[j] = 0.f;

    long long last = (long long)(H - 1) * F2 + f;
    if (last < cap_w) {                          // fast path
        if (is32) {
            const float* Wf = (const float*)W;
            for (int h = 0; h < H; h++) {
                float w = Wf[(size_t)h * F2 + f];
#pragma unroll
                for (int j = 0; j < 8; j++) acc[j] += sh[j * H + h] * w;
            }
        } else {
            const __nv_bfloat16* Wb = (const __nv_bfloat16*)W;
            for (int h = 0; h < H; h++) {
                float w = __bfloat162float(Wb[(size_t)h * F2 + f]);
#pragma unroll
                for (int j = 0; j < 8; j++) acc[j] += sh[j * H + h] * w;
            }
        }
    } else {                                     // guarded slow path
        for (int h = 0; h < H; h++) {
            long long idx = (long long)h * F2 + f;
            float w = (idx < cap_w) ? load_in(W, (size_t)idx, is32) : 0.f;
#pragma unroll
            for (int j = 0; j < 8; j++) acc[j] += sh[j * H + h] * w;
        }
    }
#pragma unroll
    for (int j = 0; j < 8; j++) {
        long long vi = (long long)(b0 + j) * F2 + f;
        if (b0 + j < B && vi < V_CAP) g_v[vi] = acc[j];
    }
}

// ============================================================
// Kernel 1b: c[b] = dot(hidden[b], bias)
// ============================================================
__global__ void bias_dot_kernel(const void* hidden, const void* bias,
                                int H, long long cap_h, long long cap_b) {
    const int is32 = g_is_f32;
    const int b = blockIdx.x;
    float acc = 0.f;
    for (int h = threadIdx.x; h < H; h += 128) {
        long long hi = (long long)b * H + h;
        float hv = (hi < cap_h) ? load_in(hidden, (size_t)hi, is32) : 0.f;
        float bv = (h < cap_b) ? load_in(bias, (size_t)h, is32) : 0.f;
        acc += hv * bv;
    }
#pragma unroll
    for (int off = 16; off; off >>= 1)
        acc += __shfl_xor_sync(0xffffffffu, acc, off);
    __shared__ float ws[4];
    if ((threadIdx.x & 31) == 0) ws[threadIdx.x >> 5] = acc;
    __syncthreads();
    if (threadIdx.x == 0 && b < C_CAP)
        g_c[b] = ws[0] + ws[1] + ws[2] + ws[3];
}

// ============================================================
// Kernel 2: scores[b,s] = dot(enc[s,b,:], v[b,:])
// grid (ceil(S/16), B), 256 thr = 8 warps, 2 s per warp.
// Fast path: vectorized 16B loads (float4 / 8x bf16), 16 independent
// LDG.128 in flight per thread. Dyn smem = F2 floats (16B-aligned base).
// ============================================================
__global__ void __launch_bounds__(256, 4)
score_kernel(const void* enc, int F2, int B, int S, long long cap_e) {
    extern __shared__ float vsh[];              // F2 floats
    const int is32 = g_is_f32;
    const int b  = blockIdx.y;
    const int w  = threadIdx.x >> 5;
    const int ln = threadIdx.x & 31;
    const int s0 = blockIdx.x * 16 + 2 * w;
    const int s1 = s0 + 1;

    for (int i = threadIdx.x; i < F2; i += 256) {
        long long vi = (long long)b * F2 + i;
        vsh[i] = (vi < V_CAP) ? g_v[vi] : 0.f;
    }
    __syncthreads();
    if (s0 >= S) return;

    const long long base0 = ((long long)s0 * B + b) * F2;
    const long long base1 = ((long long)s1 * B + b) * F2;
    const bool ok1 = (s1 < S);
    float acc0 = 0.f, acc1 = 0.f;

    const bool vec_ok = (F2 % 128 == 0) && (base0 % 4 == 0) &&
                        (base0 + F2 <= cap_e) &&
                        (!ok1 || base1 + F2 <= cap_e);
    if (vec_ok) {
        const int nIter = F2 >> 7;               // F2 / 128
        const float4* vs4 = (const float4*)vsh;  // dyn smem base 16B-aligned
        if (is32) {
            const float4* p0 = (const float4*)((const float*)enc + base0);
            const float4* p1 = (const float4*)((const float*)enc + base1);
            for (int i = 0; i < nIter; i++) {
                int k = i * 32 + ln;
                float4 v = vs4[k];
                float4 e0 = p0[k];
                acc0 += e0.x * v.x + e0.y * v.y + e0.z * v.z + e0.w * v.w;
                if (ok1) {
                    float4 e1 = p1[k];
                    acc1 += e1.x * v.x + e1.y * v.y + e1.z * v.z + e1.w * v.w;
                }
            }
        } else {
            // 16B = 8 bf16 per load; F2 % 128 == 0 guarantees 2 vsh float4 per load
            const int nIter8 = F2 >> 8;          // F2 / 256
            const uint4* p0 = (const uint4*)((const __nv_bfloat16*)enc + base0);
            const uint4* p1 = (const uint4*)((const __nv_bfloat16*)enc + base1);
            for (int i = 0; i < nIter8; i++) {
                int k = i * 32 + ln;
                uint4 e0 = p0[k];
                float4 va = vs4[2 * k], vb = vs4[2 * k + 1];
                const __nv_bfloat162* c0 = (const __nv_bfloat162*)&e0;
                float2 f0 = __bfloat1622float2(c0[0]);
                float2 f1 = __bfloat1622float2(c0[1]);
                float2 f2 = __bfloat1622float2(c0[2]);
                float2 f3 = __bfloat1622float2(c0[3]);
                acc0 += f0.x * va.x + f0.y * va.y + f1.x * va.z + f1.y * va.w
                      + f2.x * vb.x + f2.y * vb.y + f3.x * vb.z + f3.y * vb.w;
                if (ok1) {
                    uint4 e1 = p1[k];
                    const __nv_bfloat162* c1 = (const __nv_bfloat162*)&e1;
                    float2 g0 = __bfloat1622float2(c1[0]);
                    float2 g1 = __bfloat1622float2(c1[1]);
                    float2 g2 = __bfloat1622float2(c1[2]);
                    float2 g3 = __bfloat1622float2(c1[3]);
                    acc1 += g0.x * va.x + g0.y * va.y + g1.x * va.z + g1.y * va.w
                          + g2.x * vb.x + g2.y * vb.y + g3.x * vb.z + g3.y * vb.w;
                }
            }
        }
    } else {                                     // guarded scalar fallback
        for (int k = ln; k < F2; k += 32) {
            long long i0 = base0 + k;
            if (i0 >= 0 && i0 < cap_e)
                acc0 += load_in(enc, (size_t)i0, is32) * vsh[k];
            if (ok1) {
                long long i1 = base1 + k;
                if (i1 >= 0 && i1 < cap_e)
                    acc1 += load_in(enc, (size_t)i1, is32) * vsh[k];
            }
        }
    }
#pragma unroll
    for (int off = 16; off; off >>= 1) {
        acc0 += __shfl_xor_sync(0xffffffffu, acc0, off);
        acc1 += __shfl_xor_sync(0xffffffffu, acc1, off);
    }
    if (ln == 0) {
        long long si0 = (long long)b * S + s0;
        if (si0 < SC_CAP) g_scores[si0] = acc0;
        if (ok1) {
            long long si1 = (long long)b * S + s1;
            if (si1 < SC_CAP) g_scores[si1] = acc1;
        }
    }
}

// ============================================================
// Kernel 3: softmax over S per batch. grid B, 256 thr, dyn smem S floats.
// ============================================================
__global__ void softmax_kernel(void* out, int S, long long out_cap) {
    extern __shared__ float sc[];
    __shared__ float red[8];
    const int is32 = g_is_f32;
    const int b = blockIdx.x;
    const int t = threadIdx.x;
    const float c = (b < C_CAP) ? g_c[b] : 0.f;

    float m = -INFINITY;
    for (int i = t; i < S; i += 256) {
        long long si = (long long)b * S + i;
        float v = ((si < SC_CAP) ? g_scores[si] : 0.f) + c;
        sc[i] = v;
        m = fmaxf(m, v);
    }
#pragma unroll
    for (int off = 16; off; off >>= 1)
        m = fmaxf(m, __shfl_xor_sync(0xffffffffu, m, off));
    if ((t & 31) == 0) red[t >> 5] = m;
    __syncthreads();
    if (t < 8) {
        float mm = red[t];
#pragma unroll
        for (int off = 4; off; off >>= 1)
            mm = fmaxf(mm, __shfl_xor_sync(0xffu, mm, off));
        red[t] = mm;
    }
    __syncthreads();
    m = red[0];
    __syncthreads();

    float sum = 0.f;
    for (int i = t; i < S; i += 256) {
        float e = __expf(sc[i] - m);
        sc[i] = e;
        sum += e;
    }
#pragma unroll
    for (int off = 16; off; off >>= 1)
        sum += __shfl_xor_sync(0xffffffffu, sum, off);
    __shared__ float red2[8];
    if ((t & 31) == 0) red2[t >> 5] = sum;
    __syncthreads();
    if (t < 8) {
        float ss = red2[t];
#pragma unroll
        for (int off = 4; off; off >>= 1)
            ss += __shfl_xor_sync(0xffu, ss, off);
        red2[t] = ss;
    }
    __syncthreads();
    const float inv = 1.f / red2[0];

    for (int i = t; i < S; i += 256) {
        long long oi = (long long)b * S + i;
        if (oi < out_cap) {
            float r = sc[i] * inv;
            if (is32) ((float*)out)[oi] = r;
            else      ((__nv_bfloat16*)out)[oi] = __float2bfloat16(r);
        }
    }
}

// ============================================================
extern "C" void kernel_launch(void* const* d_in, const int* in_sizes, int n_in,
                              void* d_out, int out_size) {
    if (n_in < 4) return;

    long long sz[16];
    int ord[16];
    int m = n_in > 16 ? 16 : n_in;
    for (int i = 0; i < m; i++) {
        sz[i] = in_sizes[i] > 0 ? (long long)in_sizes[i] : 0;
        ord[i] = i;
    }
    for (int i = 0; i < m; i++)
        for (int j = i + 1; j < m; j++)
            if (sz[ord[j]] < sz[ord[i]]) { int t = ord[i]; ord[i] = ord[j]; ord[j] = t; }
    int ib = ord[m - 4], ih = ord[m - 3], iw = ord[m - 2], ie = ord[m - 1];
    long long nb = sz[ib], nh = sz[ih], nw = sz[iw], ne = sz[ie];

    // Jointly solve unit (elements / f32-bytes / bf16-bytes) and shapes:
    //   H = nb/u;  nw/u == 2*H*H;  B = (nh/u)/H;  S = (ne/u)/(B*2H)
    long long H = 0, B = 0, S = 0, unit = 0;
    const long long units[3] = {1, 4, 2};
    for (int k = 0; k < 3; k++) {
        long long u = units[k];
        if (nb % u || nh % u || nw % u || ne % u) continue;
        long long Hh = nb / u;
        if (Hh <= 0 || Hh > 65536) continue;
        if (nw / u != 2 * Hh * Hh) continue;
        if ((nh / u) % Hh) continue;
        long long Bb = (nh / u) / Hh;
        if (Bb <= 0 || Bb > 65535) continue;
        long long f2 = 2 * Hh;
        if ((ne / u) % (Bb * f2)) continue;
        long long Ss = (ne / u) / (Bb * f2);
        if (Ss <= 0) continue;
        H = Hh; B = Bb; S = Ss; unit = u;
        break;
    }
    if (unit == 0) { H = 512; B = 64; S = 2048; unit = 1; }
    const int F2 = (int)(2 * H);

    const void* bias   = d_in[ib];
    const void* hidden = d_in[ih];
    const void* W      = d_in[iw];
    const void* enc    = d_in[ie];
    long long cap_b = nb / unit, cap_h = nh / unit;
    long long cap_w = nw / unit, cap_e = ne / unit;
    long long out_cap = out_size > 0 ? (long long)out_size : 0;

    detect_kernel<<<1, 128>>>(enc, cap_e);

    dim3 g1((unsigned)((F2 + 127) / 128), (unsigned)((B + 7) / 8));
    proj_kernel<<<g1, 128, (size_t)(8 * H) * 4>>>(hidden, W, (int)H, F2, (int)B,
                                                  cap_h, cap_w);
    bias_dot_kernel<<<(unsigned)B, 128>>>(hidden, bias, (int)H, cap_h, cap_b);

    dim3 g2((unsigned)((S + 15) / 16), (unsigned)B);
    score_kernel<<<g2, 256, (size_t)F2 * 4>>>(enc, F2, (int)B, (int)S, cap_e);

    softmax_kernel<<<(unsigned)B, 256, (size_t)S * 4>>>(d_out, (int)S, out_cap);
}